// round 7
// baseline (speedup 1.0000x reference)
#include <cuda_runtime.h>
#include <math.h>

// out[b,c,p,n,q] = sum_h C[n,h] * x[b,c,p,h,q]  for p<26,q<26 ; else 0.
// C (32x64) = (M32^3)^T[:, :26] @ (M64^3)[:26, :]   (host-computed in double)
//
// R6 layout: warp <-> (bc, p), lane <-> q. x goes global->register (coalesced,
// streaming), C is broadcast-read from smem as f32x2 n-pairs. No block barriers
// in the hot path, 4 blocks/SM resident.

struct CtParam { float ct[64][32]; };   // ct[h][n]

#define TPB 256

// packed fp32x2 FMA (sm_100+): d.lo += a.lo*b.lo ; d.hi += a.hi*b.hi
#define FMA2(d, a, b) asm("fma.rn.f32x2 %0, %1, %2, %0;" : "+l"(d) : "l"(a), "l"(b))
#define DUP2(d, f)    asm("mov.b64 %0, {%1, %1};" : "=l"(d) : "f"(f))

__global__ void __launch_bounds__(TPB) spectral_pool_kernel(
    const float* __restrict__ x, float* __restrict__ out,
    const __grid_constant__ CtParam cp)
{
    __shared__ ulonglong2 sC[64][8];        // == float[64][32], 8 KB

    const int tid  = threadIdx.x;
    const int bc   = blockIdx.x >> 2;       // 0..255
    const int pt   = blockIdx.x & 3;
    const int w    = tid >> 5;
    const int lane = tid & 31;
    const int p    = pt * 8 + w;            // this warp's p (0..31)

    // C -> smem (2 x float4 per thread), the only block-wide sync
    {
        const float4* src = reinterpret_cast<const float4*>(&cp.ct[0][0]);
        float4* dst = reinterpret_cast<float4*>(&sC[0][0]);
        dst[tid]       = src[tid];
        dst[tid + 256] = src[tid + 256];
    }
    __syncthreads();

    const bool act = (p < 26) && (lane < 26);   // truncation mask
    const float* xp0 = x + (size_t)bc * 262144 + (size_t)p * 4096 + lane;

    unsigned long long acc[16];             // 16 n-pairs (f32x2) for this q
#pragma unroll
    for (int i = 0; i < 16; i++) acc[i] = 0ull;

    float xr[8], xn[8];
#pragma unroll
    for (int h = 0; h < 8; h++)
        xr[h] = act ? __ldcs(xp0 + (size_t)h * 64) : 0.f;

#pragma unroll
    for (int kc = 0; kc < 8; kc++) {        // h chunks of 8
        if (kc < 7) {                       // prefetch next chunk (8 indep LDG)
#pragma unroll
            for (int h = 0; h < 8; h++)
                xn[h] = act ? __ldcs(xp0 + (size_t)((kc + 1) * 8 + h) * 64) : 0.f;
        }
#pragma unroll
        for (int hh = 0; hh < 8; hh++) {
            unsigned long long xpair;
            DUP2(xpair, xr[hh]);
#pragma unroll
            for (int j = 0; j < 8; j++) {   // broadcast LDS.128: 2 n-pairs
                ulonglong2 c2 = sC[kc * 8 + hh][j];
                FMA2(acc[2 * j],     c2.x, xpair);
                FMA2(acc[2 * j + 1], c2.y, xpair);
            }
        }
#pragma unroll
        for (int h = 0; h < 8; h++) xr[h] = xn[h];
    }

    // store column q=lane for all 32 n (pad region p>=26 / q>=26 is exact 0)
    float* ob = out + (size_t)bc * 32768 + (size_t)p * 1024 + lane;
#pragma unroll
    for (int np = 0; np < 16; np++) {
        float lo, hi;
        asm("mov.b64 {%0, %1}, %2;" : "=f"(lo), "=f"(hi) : "l"(acc[np]));
        __stcs(ob + (size_t)(2 * np) * 32,     lo);
        __stcs(ob + (size_t)(2 * np + 1) * 32, hi);
    }
}

// ---------------- host side ----------------

static void mm_d(const double* A, const double* B, double* C, int n)
{
    for (int i = 0; i < n; i++)
        for (int j = 0; j < n; j++) {
            double s = 0.0;
            for (int k = 0; k < n; k++) s += A[i * n + k] * B[k * n + j];
            C[i * n + j] = s;
        }
}

static void build_ct(CtParam* cp)
{
    static double M64[64 * 64], T64[64 * 64], P64[64 * 64];
    static double M32[32 * 32], T32[32 * 32], P32[32 * 32];

    const double PI = 3.14159265358979323846;
    for (int k = 0; k < 64; k++)
        for (int n = 0; n < 64; n++) {
            double v = sqrt(2.0 / 64.0) * cos(PI * (2.0 * n + 1.0) * k / 128.0);
            if (k == 0) v = 1.0 / 8.0;
            M64[k * 64 + n] = v;
        }
    for (int k = 0; k < 32; k++)
        for (int n = 0; n < 32; n++) {
            double v = sqrt(2.0 / 32.0) * cos(PI * (2.0 * n + 1.0) * k / 64.0);
            if (k == 0) v = 1.0 / sqrt(32.0);
            M32[k * 32 + n] = v;
        }

    mm_d(M64, M64, T64, 64);
    mm_d(T64, M64, P64, 64);     // M64^3
    mm_d(M32, M32, T32, 32);
    mm_d(T32, M32, P32, 32);     // M32^3

    for (int n = 0; n < 32; n++)
        for (int h = 0; h < 64; h++) {
            double s = 0.0;
            for (int k = 0; k < 26; k++)
                s += P32[k * 32 + n] * P64[k * 64 + h];
            cp->ct[h][n] = (float)s;
        }
}

extern "C" void kernel_launch(void* const* d_in, const int* in_sizes, int n_in,
                              void* d_out, int out_size)
{
    (void)in_sizes; (void)n_in; (void)out_size;
    const float* x = (const float*)d_in[0];
    float* out = (float*)d_out;

    static CtParam cp;
    build_ct(&cp);

    spectral_pool_kernel<<<1024, TPB>>>(x, out, cp);
}